// round 4
// baseline (speedup 1.0000x reference)
#include <cuda_runtime.h>
#include <cuda_bf16.h>

#define BATCH 8
#define FDIM 16
#define NPTS 2048
#define TILE 128
#define NTILE (NPTS / TILE)             // 16
#define NTRI  (NTILE * (NTILE + 1) / 2) // 136

typedef unsigned long long u64;

__device__ __forceinline__ float2 ffma2(float2 a, float2 b, float2 c)
{
    float2 d;
    asm("fma.rn.f32x2 %0, %1, %2, %3;"
        : "=l"(reinterpret_cast<u64&>(d))
        : "l"(reinterpret_cast<u64&>(a)),
          "l"(reinterpret_cast<u64&>(b)),
          "l"(reinterpret_cast<u64&>(c)));
    return d;
}
__device__ __forceinline__ float ex2f(float x)
{ float y; asm("ex2.approx.ftz.f32 %0, %1;" : "=f"(y) : "f"(x)); return y; }
__device__ __forceinline__ float lg2f(float x)
{ float y; asm("lg2.approx.ftz.f32 %0, %1;" : "=f"(y) : "f"(x)); return y; }

// 16B-unit index into the 64x128-float staging buffer.
// Write phase: rl = (tx&7)*8 + jj  ->  rl>>3 = tx&7 spans 0..7 across lanes,
// giving distinct low-3 xor masks -> <=2-way STS conflicts.
// Read phase: c4 = lane, fixed rl  ->  xor is a permutation -> conflict-free.
__device__ __forceinline__ int tsw(int rl, int c4)
{
    return rl * 32 + (c4 ^ ((rl >> 3) & 31));
}

// ---------------------------------------------------------------------------
// One 128x128 (i,j) tile per block, upper-triangular tiles only (it <= jt).
// 512 threads, 4x8 micro-tile. Off-diagonal tiles emit the transposed block
// via smem staging (two 64-row halves reusing the tile buffers).
// ---------------------------------------------------------------------------
__global__ __launch_bounds__(512, 2)
void qcd_main_kernel(const float* __restrict__ emb,
                     const float* __restrict__ alpha_p,
                     const float* __restrict__ beta_p,
                     float* __restrict__ out)
{
    // 32KB region: As2 (16KB) + Bs (8KB) alive through the mainloop,
    // then reused as the 64x128 float transpose staging buffer.
    __shared__ __align__(16) unsigned char smraw[32 * 1024];
    __shared__ float cni_s[TILE], pi_s[TILE], cnj_s[TILE], pj_s[TILE];

    float2 (*As2)[TILE] = reinterpret_cast<float2(*)[TILE]>(smraw);
    float  (*Bs )[TILE] = reinterpret_cast<float (*)[TILE]>(smraw + sizeof(float2) * FDIM * TILE);
    float4* Tq          = reinterpret_cast<float4*>(smraw);

    // Triangular tile index: t -> (it, jt), it <= jt
    const int t = blockIdx.x;
    int jt = (int)((sqrtf(8.0f * (float)t + 1.0f) - 1.0f) * 0.5f);
    if ((jt + 1) * (jt + 2) / 2 <= t) jt++;
    else if (jt * (jt + 1) / 2 > t)   jt--;
    const int it = t - jt * (jt + 1) / 2;

    const int b  = blockIdx.y;
    const int i0 = it * TILE;
    const int j0 = jt * TILE;
    const int tid = threadIdx.x;

    const float* eb = emb + (size_t)b * FDIM * NPTS;

    // Tile loads: 1024 float4 over 512 threads, 2 each.
#pragma unroll
    for (int k = 0; k < 2; ++k) {
        int q = tid + k * 512;
        if (q < 512) {                  // A tile, broadcast-packed
            int f  = q >> 5;
            int n4 = q & 31;
            float4 v = *(const float4*)&eb[f * NPTS + i0 + n4 * 4];
            float4* d = (float4*)&As2[f][n4 * 4];
            d[0] = make_float4(v.x, v.x, v.y, v.y);
            d[1] = make_float4(v.z, v.z, v.w, v.w);
        } else {                        // B tile
            int q2 = q - 512;
            int f  = q2 >> 5;
            int n4 = q2 & 31;
            *(float4*)&Bs[f][n4 * 4] = *(const float4*)&eb[f * NPTS + j0 + n4 * 4];
        }
    }
    __syncthreads();

    // Norms (pre-scaled by c = -beta^2*log2e) and m^(2*alpha)
    const float alpha2 = 2.0f * alpha_p[0];
    const float beta   = beta_p[0];
    const float cl     = -(beta * beta) * 1.4426950408889634f;
    const float m2cl   = -2.0f * cl;
    if (tid < 128) {
        float s = 0.0f;
#pragma unroll
        for (int f = 0; f < FDIM; ++f) { float v = As2[f][tid].x; s = fmaf(v, v, s); }
        cni_s[tid] = cl * s;
        pi_s[tid]  = ex2f(alpha2 * lg2f(As2[4][tid].x));
    } else if (tid < 256) {
        int tt = tid - 128;
        float s = 0.0f;
#pragma unroll
        for (int f = 0; f < FDIM; ++f) { float v = Bs[f][tt]; s = fmaf(v, v, s); }
        cnj_s[tt] = cl * s;
        pj_s[tt]  = ex2f(alpha2 * lg2f(Bs[4][tt]));
    }
    __syncthreads();

    const int tx = tid & 15;   // j sub-tile: cols tx*8 .. +7
    const int ty = tid >> 4;   // i sub-tile: rows ty*4 .. +3 (0..31)

    float2 acc[4][4];
#pragma unroll
    for (int ii = 0; ii < 4; ++ii)
#pragma unroll
        for (int jj = 0; jj < 4; ++jj) acc[ii][jj] = make_float2(0.0f, 0.0f);

#pragma unroll
    for (int f = 0; f < FDIM; ++f) {
        float4 p0 = *(const float4*)&As2[f][ty * 4];       // (a0,a0,a1,a1)
        float4 p1 = *(const float4*)&As2[f][ty * 4 + 2];   // (a2,a2,a3,a3)
        float2 av[4] = { make_float2(p0.x, p0.y), make_float2(p0.z, p0.w),
                         make_float2(p1.x, p1.y), make_float2(p1.z, p1.w) };
        float4 q0 = *(const float4*)&Bs[f][tx * 8];
        float4 q1 = *(const float4*)&Bs[f][tx * 8 + 4];
        float2 bv[4] = { make_float2(q0.x, q0.y), make_float2(q0.z, q0.w),
                         make_float2(q1.x, q1.y), make_float2(q1.z, q1.w) };
#pragma unroll
        for (int ii = 0; ii < 4; ++ii)
#pragma unroll
            for (int jj = 0; jj < 4; ++jj)
                acc[ii][jj] = ffma2(av[ii], bv[jj], acc[ii][jj]);
    }

    float cni[4], pi[4];
#pragma unroll
    for (int k = 0; k < 4; ++k) {
        cni[k] = cni_s[ty * 4 + k];
        pi[k]  = pi_s [ty * 4 + k];
    }
    float cnj[8], pj[8];
#pragma unroll
    for (int k = 0; k < 8; ++k) {
        cnj[k] = cnj_s[tx * 8 + k];
        pj[k]  = pj_s [tx * 8 + k];
    }

    // Direct (i,j) block store
    float* orow = out + (size_t)b * NPTS * NPTS + (size_t)(i0 + ty * 4) * NPTS + j0 + tx * 8;
#pragma unroll
    for (int ii = 0; ii < 4; ++ii) {
        float w[8];
#pragma unroll
        for (int jj = 0; jj < 4; ++jj) {
            float2 g = acc[ii][jj];
            int je = jj * 2;
            float x0 = fmaf(m2cl, g.x, cni[ii] + cnj[je]);
            float x1 = fmaf(m2cl, g.y, cni[ii] + cnj[je + 1]);
            w[je]     = ex2f(fminf(pi[ii], pj[je])     * x0);
            w[je + 1] = ex2f(fminf(pi[ii], pj[je + 1]) * x1);
        }
        float4* dst = (float4*)(orow + (size_t)ii * NPTS);
        dst[0] = make_float4(w[0], w[1], w[2], w[3]);
        dst[1] = make_float4(w[4], w[5], w[6], w[7]);
    }

    // Mirror (j,i) block for off-diagonal tiles, staged 64 rows per half.
    if (it != jt) {
        const int h_own = tx >> 3;
#pragma unroll
        for (int h = 0; h < 2; ++h) {
            __syncthreads();   // tiles/previous half fully consumed
            if (h_own == h) {
#pragma unroll
                for (int jj = 0; jj < 8; ++jj) {
                    int rl = (tx & 7) * 8 + jj;
                    float wc[4];
#pragma unroll
                    for (int ii = 0; ii < 4; ++ii) {
                        float g = (jj & 1) ? acc[ii][jj >> 1].y : acc[ii][jj >> 1].x;
                        float x = fmaf(m2cl, g, cni[ii] + cnj[jj]);
                        wc[ii]  = ex2f(fminf(pi[ii], pj[jj]) * x);
                    }
                    Tq[tsw(rl, ty)] = make_float4(wc[0], wc[1], wc[2], wc[3]);
                }
            }
            __syncthreads();
            // Readback: 64 rows x 32 float4 = 2048 float4, 4 per thread.
#pragma unroll
            for (int k = 0; k < 4; ++k) {
                int idx = tid + k * 512;
                int rl  = idx >> 5;
                int c4  = idx & 31;
                float* mrow = out + (size_t)b * NPTS * NPTS
                                  + (size_t)(j0 + h * 64 + rl) * NPTS + i0;
                *(float4*)(mrow + c4 * 4) = Tq[tsw(rl, c4)];
            }
        }
    }
}

// ---------------------------------------------------------------------------
extern "C" void kernel_launch(void* const* d_in, const int* in_sizes, int n_in,
                              void* d_out, int out_size)
{
    const float* emb     = (const float*)d_in[0];
    const float* alpha_p = (const float*)d_in[1];
    const float* beta_p  = (const float*)d_in[2];
    float* out = (float*)d_out;

    dim3 grid(NTRI, BATCH);   // 136 x 8 = 1088 CTAs
    qcd_main_kernel<<<grid, 512>>>(emb, alpha_p, beta_p, out);
}

// round 5
// speedup vs baseline: 1.1342x; 1.1342x over previous
#include <cuda_runtime.h>
#include <cuda_bf16.h>

#define BATCH 8
#define FDIM 16
#define NPTS 2048
#define TILE 128
#define NTILE (NPTS / TILE)             // 16
#define NTRI  (NTILE * (NTILE + 1) / 2) // 136

__device__ __forceinline__ float ex2f(float x)
{ float y; asm("ex2.approx.ftz.f32 %0, %1;" : "=f"(y) : "f"(x)); return y; }
__device__ __forceinline__ float lg2f(float x)
{ float y; asm("lg2.approx.ftz.f32 %0, %1;" : "=f"(y) : "f"(x)); return y; }

// 16B-unit index into the 64x128-float staging buffer.
// Write phase: rl = (tx&7)*8 + jj -> rl>>2 varies across lanes -> <=2-way STS.
// Read phase: fixed rl, c4 = lane -> xor is a permutation -> conflict-free.
__device__ __forceinline__ int tsw(int rl, int c4)
{
    return rl * 32 + (c4 ^ ((rl >> 2) & 31));
}

// ---------------------------------------------------------------------------
// One 128x128 (i,j) tile per block, upper-triangular tiles only (it <= jt).
// 256 threads, 8x8 micro-tile, scalar-FFMA mainloop (minimal LDS ops).
// Off-diagonal tiles emit the transposed block via smem staging.
// ---------------------------------------------------------------------------
__global__ __launch_bounds__(256, 2)
void qcd_main_kernel(const float* __restrict__ emb,
                     const float* __restrict__ alpha_p,
                     const float* __restrict__ beta_p,
                     float* __restrict__ out)
{
    // 32KB region: As (8KB) + Bs (8KB) alive through the mainloop,
    // then reused as the 64x128 float transpose staging buffer.
    __shared__ __align__(16) unsigned char smraw[32 * 1024];
    __shared__ float cni_s[TILE], pi_s[TILE], cnj_s[TILE], pj_s[TILE];

    float (*As)[TILE] = reinterpret_cast<float(*)[TILE]>(smraw);
    float (*Bs)[TILE] = reinterpret_cast<float(*)[TILE]>(smraw + sizeof(float) * FDIM * TILE);
    float4* Tq        = reinterpret_cast<float4*>(smraw);

    // Triangular tile index: t -> (it, jt), it <= jt
    const int t = blockIdx.x;
    int jt = (int)((sqrtf(8.0f * (float)t + 1.0f) - 1.0f) * 0.5f);
    if ((jt + 1) * (jt + 2) / 2 <= t) jt++;
    else if (jt * (jt + 1) / 2 > t)   jt--;
    const int it = t - jt * (jt + 1) / 2;

    const int b  = blockIdx.y;
    const int i0 = it * TILE;
    const int j0 = jt * TILE;
    const int tid = threadIdx.x;

    const float* eb = emb + (size_t)b * FDIM * NPTS;

    // Tile loads: 2x (16 rows x 32 float4) over 256 threads, 4 float4 each.
#pragma unroll
    for (int k = 0; k < 2; ++k) {
        int q  = tid + k * 256;     // 0..511
        int f  = q >> 5;
        int n4 = q & 31;
        *(float4*)&As[f][n4 * 4] = *(const float4*)&eb[f * NPTS + i0 + n4 * 4];
        *(float4*)&Bs[f][n4 * 4] = *(const float4*)&eb[f * NPTS + j0 + n4 * 4];
    }
    __syncthreads();

    // Norms (pre-scaled by c = -beta^2*log2e) and m^(2*alpha)
    const float alpha2 = 2.0f * alpha_p[0];
    const float beta   = beta_p[0];
    const float cl     = -(beta * beta) * 1.4426950408889634f;
    const float m2cl   = -2.0f * cl;
    if (tid < 128) {
        float s = 0.0f;
#pragma unroll
        for (int f = 0; f < FDIM; ++f) { float v = As[f][tid]; s = fmaf(v, v, s); }
        cni_s[tid] = cl * s;
        pi_s[tid]  = ex2f(alpha2 * lg2f(As[4][tid]));
    } else {
        int tt = tid - 128;
        float s = 0.0f;
#pragma unroll
        for (int f = 0; f < FDIM; ++f) { float v = Bs[f][tt]; s = fmaf(v, v, s); }
        cnj_s[tt] = cl * s;
        pj_s[tt]  = ex2f(alpha2 * lg2f(Bs[4][tt]));
    }
    __syncthreads();

    const int tx = tid & 15;   // j sub-tile: cols tx*8 .. +7
    const int ty = tid >> 4;   // i sub-tile: rows ty*8 .. +7

    float acc[8][8];
#pragma unroll
    for (int ii = 0; ii < 8; ++ii)
#pragma unroll
        for (int jj = 0; jj < 8; ++jj) acc[ii][jj] = 0.0f;

    // Scalar mainloop: 4 LDS.128 + 64 FFMA per f-step (minimal MIO per MAC).
#pragma unroll
    for (int f = 0; f < FDIM; ++f) {
        float4 a0 = *(const float4*)&As[f][ty * 8];
        float4 a1 = *(const float4*)&As[f][ty * 8 + 4];
        float4 b0 = *(const float4*)&Bs[f][tx * 8];
        float4 b1 = *(const float4*)&Bs[f][tx * 8 + 4];
        float av[8] = {a0.x, a0.y, a0.z, a0.w, a1.x, a1.y, a1.z, a1.w};
        float bv[8] = {b0.x, b0.y, b0.z, b0.w, b1.x, b1.y, b1.z, b1.w};
#pragma unroll
        for (int ii = 0; ii < 8; ++ii)
#pragma unroll
            for (int jj = 0; jj < 8; ++jj)
                acc[ii][jj] = fmaf(av[ii], bv[jj], acc[ii][jj]);
    }

    float cni[8], pi[8], cnj[8], pj[8];
#pragma unroll
    for (int k = 0; k < 8; ++k) {
        cni[k] = cni_s[ty * 8 + k];
        pi[k]  = pi_s [ty * 8 + k];
        cnj[k] = cnj_s[tx * 8 + k];
        pj[k]  = pj_s [tx * 8 + k];
    }

    // Direct (i,j) block store
    float* orow = out + (size_t)b * NPTS * NPTS + (size_t)(i0 + ty * 8) * NPTS + j0 + tx * 8;
#pragma unroll
    for (int ii = 0; ii < 8; ++ii) {
        float w[8];
#pragma unroll
        for (int jj = 0; jj < 8; ++jj) {
            float x = fmaf(m2cl, acc[ii][jj], cni[ii] + cnj[jj]);
            w[jj]   = ex2f(fminf(pi[ii], pj[jj]) * x);
        }
        float4* dst = (float4*)(orow + (size_t)ii * NPTS);
        dst[0] = make_float4(w[0], w[1], w[2], w[3]);
        dst[1] = make_float4(w[4], w[5], w[6], w[7]);
    }

    // Mirror (j,i) block for off-diagonal tiles, staged 64 rows per half.
    if (it != jt) {
        const int h_own = tx >> 3;
#pragma unroll
        for (int h = 0; h < 2; ++h) {
            __syncthreads();   // tiles / previous half fully consumed
            if (h_own == h) {
                // Transposed write: recompute w per column from acc (ALU/MUFU,
                // no extra MIO beyond the STS).
#pragma unroll
                for (int jj = 0; jj < 8; ++jj) {
                    int rl = (tx & 7) * 8 + jj;
                    float wc[8];
#pragma unroll
                    for (int ii = 0; ii < 8; ++ii) {
                        float x = fmaf(m2cl, acc[ii][jj], cni[ii] + cnj[jj]);
                        wc[ii]  = ex2f(fminf(pi[ii], pj[jj]) * x);
                    }
                    Tq[tsw(rl, 2 * ty + 0)] = make_float4(wc[0], wc[1], wc[2], wc[3]);
                    Tq[tsw(rl, 2 * ty + 1)] = make_float4(wc[4], wc[5], wc[6], wc[7]);
                }
            }
            __syncthreads();
            // Coalesced readback + store: 64 rows x 32 float4, 8 per thread.
#pragma unroll
            for (int m = 0; m < 2; ++m) {
                int rl  = m * 32 + (tid >> 3);
                float* mrow = out + (size_t)b * NPTS * NPTS
                                  + (size_t)(j0 + h * 64 + rl) * NPTS + i0;
#pragma unroll
                for (int k = 0; k < 4; ++k) {
                    int c4 = (tid & 7) + k * 8;
                    *(float4*)(mrow + c4 * 4) = Tq[tsw(rl, c4)];
                }
            }
        }
    }
}

// ---------------------------------------------------------------------------
extern "C" void kernel_launch(void* const* d_in, const int* in_sizes, int n_in,
                              void* d_out, int out_size)
{
    const float* emb     = (const float*)d_in[0];
    const float* alpha_p = (const float*)d_in[1];
    const float* beta_p  = (const float*)d_in[2];
    float* out = (float*)d_out;

    dim3 grid(NTRI, BATCH);   // 136 x 8 = 1088 CTAs
    qcd_main_kernel<<<grid, 256>>>(emb, alpha_p, beta_p, out);
}